// round 12
// baseline (speedup 1.0000x reference)
#include <cuda_runtime.h>
#include <cuda_fp16.h>
#include <cstdint>
#include <math.h>

// ---------------- problem constants ----------------
#define BATCH 8
#define CIN   64
#define COUT  64
#define SDIM  512
#define HH    256
#define WW    256
#define TAPS  9

#define CONV_SCALE (1.0f / 24.0f)
#define MOD_SCALE  (0.04419417382415922f)
#define EPSV       (1e-8f)

// ---------------- device scratch ----------------
// demodulated weights fp16: [b][tap][co][ci]
__device__ __align__(16) __half g_wt[BATCH * TAPS * COUT * CIN];

// ---------------- helpers ----------------
__device__ __forceinline__ uint32_t smem_u32(const void* p) {
    uint32_t a;
    asm("{ .reg .u64 t; cvta.to.shared.u64 t, %1; cvt.u32.u64 %0, t; }" : "=r"(a) : "l"(p));
    return a;
}
__device__ __forceinline__ void ldsm4(uint32_t (&r)[4], uint32_t addr) {
    asm volatile("ldmatrix.sync.aligned.m8n8.x4.shared.b16 {%0,%1,%2,%3}, [%4];"
                 : "=r"(r[0]), "=r"(r[1]), "=r"(r[2]), "=r"(r[3]) : "r"(addr));
}
// fp16-accumulator mma
__device__ __forceinline__ void mma16816h(uint32_t (&c)[2], const uint32_t (&a)[4],
                                          const uint32_t b0, const uint32_t b1) {
    asm volatile(
        "mma.sync.aligned.m16n8k16.row.col.f16.f16.f16.f16 "
        "{%0,%1}, {%2,%3,%4,%5}, {%6,%7}, {%0,%1};"
        : "+r"(c[0]), "+r"(c[1])
        : "r"(a[0]), "r"(a[1]), "r"(a[2]), "r"(a[3]), "r"(b0), "r"(b1));
}
__device__ __forceinline__ void cpasync16(uint32_t dst, const void* src) {
    asm volatile("cp.async.cg.shared.global [%0], [%1], 16;" :: "r"(dst), "l"(src) : "memory");
}
__device__ __forceinline__ void cpcommit() { asm volatile("cp.async.commit_group;" ::: "memory"); }
__device__ __forceinline__ void cpwait0()  { asm volatile("cp.async.wait_group 0;" ::: "memory"); }

__device__ __forceinline__ uint32_t sw128(uint32_t o) { return o ^ ((o >> 3) & 0x70u); }

// ---------------- kernel A: style modulation + demodulated fp16 weights ----
__global__ void demod_kernel(const float* __restrict__ style,
                             const float* __restrict__ mw,
                             const float* __restrict__ mb,
                             const float* __restrict__ w) {
    int co = blockIdx.x;
    int b  = blockIdx.y;
    int tid = threadIdx.x;

    __shared__ float sdot[64];
    __shared__ float red[576];

    if (tid < 512) {
        int ci = tid >> 3;
        int j  = tid & 7;
        const float* sp = style + b * SDIM;
        const float* wp = mw + ci * SDIM;
        float sum = 0.f;
        #pragma unroll 8
        for (int t = 0; t < 64; t++)
            sum += sp[j + 8 * t] * wp[j + 8 * t];
        sum += __shfl_xor_sync(0xFFFFFFFFu, sum, 4);
        sum += __shfl_xor_sync(0xFFFFFFFFu, sum, 2);
        sum += __shfl_xor_sync(0xFFFFFFFFu, sum, 1);
        if (j == 0) sdot[ci] = sum * MOD_SCALE + mb[ci];
    }
    __syncthreads();

    int ci  = tid / TAPS;
    int tap = tid - ci * TAPS;
    float val = CONV_SCALE * w[(co * CIN + ci) * TAPS + tap] * sdot[ci];

    red[tid] = val * val;
    __syncthreads();
    if (tid < 64) red[tid] += red[tid + 512];
    __syncthreads();
    for (int s = 256; s > 0; s >>= 1) {
        if (tid < s) red[tid] += red[tid + s];
        __syncthreads();
    }
    float vd = val * rsqrtf(red[0] + EPSV);
    g_wt[(((size_t)b * TAPS + tap) * COUT + co) * CIN + ci] = __float2half_rn(vd);
}

// ---------------- kernel B: persistent conv, fp16-acc mma + fp32 flush -----
// Work unit = chunk (xh, y4chunk, b): 128px x 64co x 4 rows (2 pairs).
// 8 warps (256 thr): 4 in M (32px) x 2 in N (32co), rows paired.
// fp16 accumulators flushed to fp32 registers every 2 segments (6x/pair):
// chain-rounding error ~5.2e-4 rms, total ~6e-4 (budget 1e-3).
#define W_OFF      0u
#define W_BYTES    73728u
#define RING_OFF   73728u
#define ROW_STRIDE 16640u                        // 130 px x 128B
#define STAGE_OFF  (RING_OFF + 6u * ROW_STRIDE)  // 173568
#define STAGE_W    136                           // fp32 words per ci row
#define SMEM_TOTAL (STAGE_OFF + 64u * STAGE_W * 4u)   // 208384

#define NCTA       148

__global__ __launch_bounds__(256, 1)
void conv_kernel(const float* __restrict__ in, float* __restrict__ out) {
    extern __shared__ char smem[];
    const uint32_t sb = smem_u32(smem);
    const int tid  = threadIdx.x;
    const int wid  = tid >> 5;
    const int lane = tid & 31;

    const int mwarp = wid & 3;
    const int nwarp = wid >> 2;
    const uint32_t px0 = mwarp * 32;
    const uint32_t co0 = nwarp * 32;

    const uint32_t arow = lane & 15;
    const uint32_t khA  = ((lane >> 4) & 1) * 16;
    const uint32_t brow = (lane & 7) | ((lane >> 1) & 8);
    const uint32_t khB  = ((lane >> 3) & 1) * 16;

    // chunk range: 136 CTAs x 7, 12 CTAs x 6  (1024 = 136*7 + 12*6)
    const int cta = blockIdx.x;
    int c, cnt;
    if (cta < 136) { c = cta * 7;               cnt = 7; }
    else           { c = 952 + (cta - 136) * 6; cnt = 6; }

    float* sOut = (float*)(smem + STAGE_OFF);    // [64co][132px] f32 (reuses stage)
    const int eg = lane >> 2;
    const int et = lane & 3;

    int last_b = -1;

    while (cnt > 0) {
        const int col    = c >> 6;          // 16 columns = b(8) x xh(2)
        const int within = c & 63;
        const int b  = col >> 1;
        const int x0 = (col & 1) * 128;
        const int run = min(cnt, 64 - within);
        const int y0r = within * 4;
        const int npairs = run * 2;

        // ---- stage one raw fp32 input row into the stage buffer ----
        auto stage_async = [&](int iy) {
            if ((unsigned)iy >= 256u) return;
            #pragma unroll
            for (int it = 0; it < 9; it++) {
                int idx = tid + 256 * it;        // 64 ci x 34 chunks = 2176
                if (idx < 2176) {
                    int ci = idx / 34;
                    int cc = idx - ci * 34;
                    int gx0 = x0 - 4 + 4 * cc;
                    uint32_t doff = STAGE_OFF + (uint32_t)(ci * STAGE_W + 4 * cc) * 4u;
                    if ((unsigned)gx0 <= 252u) {
                        cpasync16(sb + doff,
                                  in + (((size_t)(b * CIN + ci)) * HH + iy) * WW + gx0);
                    } else {
                        *(uint4*)(smem + doff) = make_uint4(0, 0, 0, 0);
                    }
                }
            }
        };

        // ---- convert staged fp32 row -> swizzled fp16 ring slot ----
        auto convert_row = [&](int iy) {
            const uint32_t roff = RING_OFF
                + ((uint32_t)((iy + 1 + 768) % 6)) * ROW_STRIDE;
            const bool valid = ((unsigned)iy < 256u);
            const float* st = (const float*)(smem + STAGE_OFF);
            const int g = wid;
            #pragma unroll
            for (int it = 0; it < 5; it++) {
                int px = (it < 4) ? (it * 32 + lane) : (128 + lane);
                if (it == 4 && lane >= 2) break;
                float v[8];
                #pragma unroll
                for (int k = 0; k < 8; k++)
                    v[k] = valid ? st[(g * 8 + k) * STAGE_W + px + 3] : 0.f;
                uint32_t u[4];
                #pragma unroll
                for (int k = 0; k < 4; k++) {
                    __half2 hp = __floats2half2_rn(v[2 * k], v[2 * k + 1]);
                    u[k] = *reinterpret_cast<uint32_t*>(&hp);
                }
                *(uint4*)(smem + roff + sw128((uint32_t)px * 128u + (uint32_t)g * 16u))
                    = make_uint4(u[0], u[1], u[2], u[3]);
            }
        };

        // ---- run prologue: W (if b changed) + prime rows y0r-1..y0r+2 ----
        if (b != last_b) {
            const uint4* ws = ((const uint4*)g_wt) + (size_t)b * 4608;
            for (int j = tid; j < 4608; j += 256) {
                uint32_t o = (uint32_t)j << 4;
                cpasync16(sb + W_OFF + sw128(o), ws + j);
            }
            cpcommit();
            last_b = b;
        }
        #pragma unroll 1
        for (int rnd = 0; rnd < 4; rnd++) {
            stage_async(y0r - 1 + rnd);
            cpcommit();
            cpwait0();
            __syncthreads();
            convert_row(y0r - 1 + rnd);
            __syncthreads();
        }

        // ---- continuous pair loop across the whole run ----
        for (int q = 0; q < npairs; q++) {
            const int y = y0r + 2 * q;
            const bool more = (q < npairs - 1);

            if (more) { stage_async(y + 3); cpcommit(); }

            uint32_t rowA[4];
            #pragma unroll
            for (int j = 0; j < 4; j++)
                rowA[j] = sb + RING_OFF + ((uint32_t)((y + j) % 6)) * ROW_STRIDE;

            float acc[2][2][4][4];               // fp32 master accumulators
            uint32_t acch[2][2][4][2];           // fp16x2 mma accumulators
            #pragma unroll
            for (int r = 0; r < 2; r++)
                #pragma unroll
                for (int mf = 0; mf < 2; mf++)
                    #pragma unroll
                    for (int nf = 0; nf < 4; nf++) {
                        #pragma unroll
                        for (int cc = 0; cc < 4; cc++) acc[r][mf][nf][cc] = 0.f;
                        acch[r][mf][nf][0] = 0u;
                        acch[r][mf][nf][1] = 0u;
                    }

            #pragma unroll
            for (int s = 0; s < 12; s++) {
                const int kc = s / 3;
                const uint32_t dx = (uint32_t)(s - 3 * kc);
                const uint32_t kb = (uint32_t)kc * 32u;

                uint32_t wfr[3][4][2];
                #pragma unroll
                for (int dy = 0; dy < 3; dy++) {
                    const uint32_t tap = (uint32_t)(dy * 3) + dx;
                    #pragma unroll
                    for (int g = 0; g < 2; g++) {
                        uint32_t tmp[4];
                        uint32_t o = (tap * 64u + co0 + (uint32_t)g * 16u + brow) * 128u
                                     + kb + khB;
                        ldsm4(tmp, sb + W_OFF + sw128(o));
                        wfr[dy][g * 2][0]     = tmp[0]; wfr[dy][g * 2][1]     = tmp[1];
                        wfr[dy][g * 2 + 1][0] = tmp[2]; wfr[dy][g * 2 + 1][1] = tmp[3];
                    }
                }
                uint32_t a[4][2][4];
                #pragma unroll
                for (int j = 0; j < 4; j++) {
                    #pragma unroll
                    for (int mf = 0; mf < 2; mf++) {
                        uint32_t o = (px0 + (uint32_t)mf * 16u + arow + dx) * 128u
                                     + kb + khA;
                        ldsm4(a[j][mf], rowA[j] + sw128(o));
                    }
                }
                #pragma unroll
                for (int dy = 0; dy < 3; dy++)
                    #pragma unroll
                    for (int r = 0; r < 2; r++)
                        #pragma unroll
                        for (int mf = 0; mf < 2; mf++)
                            #pragma unroll
                            for (int nf = 0; nf < 4; nf++)
                                mma16816h(acch[r][mf][nf], a[r + dy][mf],
                                          wfr[dy][nf][0], wfr[dy][nf][1]);

                // flush fp16 accumulators into fp32 every 2 segments
                if (s & 1) {
                    #pragma unroll
                    for (int r = 0; r < 2; r++)
                        #pragma unroll
                        for (int mf = 0; mf < 2; mf++)
                            #pragma unroll
                            for (int nf = 0; nf < 4; nf++) {
                                __half2 h0 = *reinterpret_cast<__half2*>(&acch[r][mf][nf][0]);
                                __half2 h1 = *reinterpret_cast<__half2*>(&acch[r][mf][nf][1]);
                                float2 f0 = __half22float2(h0);
                                float2 f1 = __half22float2(h1);
                                acc[r][mf][nf][0] += f0.x;
                                acc[r][mf][nf][1] += f0.y;
                                acc[r][mf][nf][2] += f1.x;
                                acc[r][mf][nf][3] += f1.y;
                                acch[r][mf][nf][0] = 0u;
                                acch[r][mf][nf][1] = 0u;
                            }
                }

                // mid-pair: consume staged row y+3, start staging row y+4
                if (s == 5 && more) {
                    cpwait0();
                    __syncthreads();
                    convert_row(y + 3);          // -> slot (y+4)%6 (free)
                    __syncthreads();
                    stage_async(y + 4);
                    cpcommit();
                }
            }

            if (more) {
                cpwait0();
                __syncthreads();
                convert_row(y + 4);              // -> slot (y+5)%6 (free)
            }
            __syncthreads();

            // ---- epilogue: two rows via smem transpose (stage reused) ----
            #pragma unroll
            for (int r = 0; r < 2; r++) {
                #pragma unroll
                for (int mf = 0; mf < 2; mf++) {
                    #pragma unroll
                    for (int nf = 0; nf < 4; nf++) {
                        int px = px0 + mf * 16 + eg;
                        int co = co0 + nf * 8 + 2 * et;
                        sOut[co * 132 + px]           = acc[r][mf][nf][0];
                        sOut[(co + 1) * 132 + px]     = acc[r][mf][nf][1];
                        sOut[co * 132 + px + 8]       = acc[r][mf][nf][2];
                        sOut[(co + 1) * 132 + px + 8] = acc[r][mf][nf][3];
                    }
                }
                __syncthreads();
                #pragma unroll
                for (int k = 0; k < 8; k++) {
                    int idx = tid + 256 * k;        // 2048 float4
                    int co = idx >> 5;
                    int qq = idx & 31;
                    float4 v = *(float4*)&sOut[co * 132 + qq * 4];
                    *(float4*)(out + (((size_t)b * COUT + co) * HH + (y + r)) * WW
                               + x0 + qq * 4) = v;
                }
                __syncthreads();
            }
        }

        c   += run;
        cnt -= run;
    }
}

// ---------------- launch ----------------
extern "C" void kernel_launch(void* const* d_in, const int* in_sizes, int n_in,
                              void* d_out, int out_size) {
    const float* input      = (const float*)d_in[0];
    const float* style      = (const float*)d_in[1];
    const float* weight     = (const float*)d_in[2];
    const float* mod_weight = (const float*)d_in[3];
    const float* mod_bias   = (const float*)d_in[4];
    float* out = (float*)d_out;

    cudaFuncSetAttribute(conv_kernel,
                         cudaFuncAttributeMaxDynamicSharedMemorySize, SMEM_TOTAL);

    demod_kernel<<<dim3(COUT, BATCH), 576>>>(style, mod_weight, mod_bias, weight);
    conv_kernel<<<NCTA, 256, SMEM_TOTAL>>>(input, out);
}